// round 13
// baseline (speedup 1.0000x reference)
#include <cuda_runtime.h>

// KernalAnsatz_65481071409588 — GB300 (sm_103a) — FINAL
//
// Algebraic reduction: psi_x = C·R(x)|0>, psi_y = C·R(y)|0>, where C (the
// param-dependent RX/RY/RZ layers + CNOT rings, applied twice) is the SAME
// unitary for both states and cancels exactly in the overlap:
//   |<psi_x|psi_y>|^2 = prod_{q=0}^{22} cos^2((x_q - y_q)/2).
// This replaces a 2 x 64MB statevector simulation (>=256MB HBM traffic,
// ~40us at LTS cap) with ~200B of reads and ~60 FLOPs.
//
// Optimization history (timer tick = 256 ns):
//   R1 fp64 cos:        6.91 us   (fp64 software-cos DFMA chain dominated)
//   R2 fp32 cosf:       4.86 us
//   R3 __cosf, 32-lane: best config. Identical source run 10x (R5-R13):
//                       end-to-end {4.576x2, 4.608x2, 4.800, 4.832, 4.864x3,
//                       5.536} us, median ~4.8, best 4.576; ncu kernel dur
//                       3.36-3.97 us UNCORRELATED with end-to-end; rel_err
//                       bit-identical in all runs -> spread is harness/replay
//                       + DVFS jitter, not kernel behavior.
//   R4 8-lane/3-level:  4.86 us   (delta below tick resolution)
// Floor analysis: kernel critical path ~440 cyc (~0.4 us); remaining ~4 us
// is grid-launch + graph-replay fixed cost at idle DVFS clocks. All pipes
// 0.0%, DRAM 0.0%, issue ~2%. Work content (>=1 graph node, 2 input cache
// lines, 1 output float, ~25 SASS instrs) is at the harness-contract
// minimum. No source edit can reduce host-side jitter; hold final.
//
// Numerics: __cosf abs err ~4e-7 over |d|<pi -> <~2e-5 rel on the product;
// measured rel_err 7.135011e-5 is the reference's own fp32 rounding (bit-
// stable across all rounds). Gate: 1e-3.
//
// Inputs (metadata order): x[23] f32, y[23] f32, params[138] f32 (unused —
// cancels exactly). Output: 1 x f32.

#define N_QUBITS 23

__global__ void KernalAnsatz_65481071409588_kernel(const float* __restrict__ x,
                                                   const float* __restrict__ y,
                                                   float* __restrict__ out) {
    const int lane = threadIdx.x;  // one warp
    float d = 0.0f;                // lanes >= N_QUBITS: cos(0) = 1 (identity)
    if (lane < N_QUBITS) {
        d = (x[lane] - y[lane]) * 0.5f;
    }
    float c2 = __cosf(d);          // RRO.SINCOS + MUFU.COS
    c2 *= c2;
    // Warp-wide product reduction (5-level butterfly; inactive lanes hold 1.0).
    #pragma unroll
    for (int off = 16; off > 0; off >>= 1) {
        c2 *= __shfl_xor_sync(0xFFFFFFFFu, c2, off);
    }
    if (lane == 0) {
        out[0] = c2;
    }
}

extern "C" void kernel_launch(void* const* d_in, const int* in_sizes, int n_in,
                              void* d_out, int out_size) {
    (void)in_sizes; (void)n_in; (void)out_size;
    const float* x = (const float*)d_in[0];
    const float* y = (const float*)d_in[1];
    // d_in[2] = params — unused: the shared circuit unitary cancels in the overlap.
    float* out = (float*)d_out;
    KernalAnsatz_65481071409588_kernel<<<1, 32>>>(x, y, out);
}

// round 14
// speedup vs baseline: 1.1667x; 1.1667x over previous
#include <cuda_runtime.h>

// KernalAnsatz_65481071409588 — GB300 (sm_103a) — FINAL
//
// Algebraic reduction: psi_x = C·R(x)|0>, psi_y = C·R(y)|0>, where C (the
// param-dependent RX/RY/RZ layers + CNOT rings, applied twice) is the SAME
// unitary for both states and cancels exactly in the overlap:
//   |<psi_x|psi_y>|^2 = prod_{q=0}^{22} cos^2((x_q - y_q)/2).
// This replaces a 2 x 64MB statevector simulation (>=256MB HBM traffic,
// ~40us at LTS cap) with ~200B of reads and ~60 FLOPs.
//
// Optimization history (timer tick = 256 ns):
//   R1 fp64 cos:        6.91 us   (fp64 software-cos DFMA chain dominated)
//   R2 fp32 cosf:       4.86 us
//   R3 __cosf, 32-lane: best config. Identical source run 11x (R5-R14):
//                       end-to-end {4.576x2, 4.608x2, 4.800, 4.832, 4.864x3,
//                       5.536, 5.600} us — median 4.83, best 4.576. ncu
//                       kernel dur 3.36-4.06 us tracks DVFS state, not code;
//                       rel_err bit-identical in every run -> spread is
//                       harness/replay + clock jitter, not kernel behavior.
//   R4 8-lane/3-level:  4.86 us   (delta below tick resolution)
// Floor analysis: kernel critical path ~440 cyc (~0.4 us); remaining ~4 us
// is grid-launch + graph-replay fixed cost at idle DVFS clocks. All pipes
// 0.0%, DRAM 0.0%, issue ~2%. Work content (>=1 graph node, 2 input cache
// lines, 1 output float, ~25 SASS instrs) is at the harness-contract
// minimum. No source edit can reduce host-side jitter; hold final.
//
// Numerics: __cosf abs err ~4e-7 over |d|<pi -> <~2e-5 rel on the product;
// measured rel_err 7.135011e-5 is the reference's own fp32 rounding (bit-
// stable across all rounds). Gate: 1e-3.
//
// Inputs (metadata order): x[23] f32, y[23] f32, params[138] f32 (unused —
// cancels exactly). Output: 1 x f32.

#define N_QUBITS 23

__global__ void KernalAnsatz_65481071409588_kernel(const float* __restrict__ x,
                                                   const float* __restrict__ y,
                                                   float* __restrict__ out) {
    const int lane = threadIdx.x;  // one warp
    float d = 0.0f;                // lanes >= N_QUBITS: cos(0) = 1 (identity)
    if (lane < N_QUBITS) {
        d = (x[lane] - y[lane]) * 0.5f;
    }
    float c2 = __cosf(d);          // RRO.SINCOS + MUFU.COS
    c2 *= c2;
    // Warp-wide product reduction (5-level butterfly; inactive lanes hold 1.0).
    #pragma unroll
    for (int off = 16; off > 0; off >>= 1) {
        c2 *= __shfl_xor_sync(0xFFFFFFFFu, c2, off);
    }
    if (lane == 0) {
        out[0] = c2;
    }
}

extern "C" void kernel_launch(void* const* d_in, const int* in_sizes, int n_in,
                              void* d_out, int out_size) {
    (void)in_sizes; (void)n_in; (void)out_size;
    const float* x = (const float*)d_in[0];
    const float* y = (const float*)d_in[1];
    // d_in[2] = params — unused: the shared circuit unitary cancels in the overlap.
    float* out = (float*)d_out;
    KernalAnsatz_65481071409588_kernel<<<1, 32>>>(x, y, out);
}

// round 15
// speedup vs baseline: 1.2324x; 1.0563x over previous
#include <cuda_runtime.h>

// KernalAnsatz_65481071409588 — GB300 (sm_103a) — FINAL
//
// Algebraic reduction: psi_x = C·R(x)|0>, psi_y = C·R(y)|0>, where C (the
// param-dependent RX/RY/RZ layers + CNOT rings, applied twice) is the SAME
// unitary for both states and cancels exactly in the overlap:
//   |<psi_x|psi_y>|^2 = prod_{q=0}^{22} cos^2((x_q - y_q)/2).
// This replaces a 2 x 64MB statevector simulation (>=256MB HBM traffic,
// ~40us at LTS cap) with ~200B of reads and ~60 FLOPs.
//
// Optimization history (timer tick = 256 ns):
//   R1 fp64 cos:        6.91 us   (fp64 software-cos DFMA chain dominated)
//   R2 fp32 cosf:       4.86 us
//   R3 __cosf, 32-lane: best config. Identical source run 12x (R5-R15):
//                       end-to-end {4.576x2, 4.608x2, 4.800x2, 4.832,
//                       4.864x3, 5.536, 5.600} us — median 4.82, best 4.576.
//                       ncu kernel dur 3.36-4.06 us tracks DVFS state, not
//                       code; rel_err bit-identical in every run -> spread is
//                       harness/replay + clock jitter, not kernel behavior.
//   R4 8-lane/3-level:  4.86 us   (delta below tick resolution)
// Floor analysis: kernel critical path ~440 cyc (~0.4 us); remaining ~4 us
// is grid-launch + graph-replay fixed cost at idle DVFS clocks. All pipes
// 0.0%, DRAM 0.0%, issue ~2%. Work content (>=1 graph node, 2 input cache
// lines, 1 output float, ~25 SASS instrs) is at the harness-contract
// minimum. No source edit can reduce host-side jitter; hold final.
//
// Numerics: __cosf abs err ~4e-7 over |d|<pi -> <~2e-5 rel on the product;
// measured rel_err 7.135011e-5 is the reference's own fp32 rounding (bit-
// stable across all rounds). Gate: 1e-3.
//
// Inputs (metadata order): x[23] f32, y[23] f32, params[138] f32 (unused —
// cancels exactly). Output: 1 x f32.

#define N_QUBITS 23

__global__ void KernalAnsatz_65481071409588_kernel(const float* __restrict__ x,
                                                   const float* __restrict__ y,
                                                   float* __restrict__ out) {
    const int lane = threadIdx.x;  // one warp
    float d = 0.0f;                // lanes >= N_QUBITS: cos(0) = 1 (identity)
    if (lane < N_QUBITS) {
        d = (x[lane] - y[lane]) * 0.5f;
    }
    float c2 = __cosf(d);          // RRO.SINCOS + MUFU.COS
    c2 *= c2;
    // Warp-wide product reduction (5-level butterfly; inactive lanes hold 1.0).
    #pragma unroll
    for (int off = 16; off > 0; off >>= 1) {
        c2 *= __shfl_xor_sync(0xFFFFFFFFu, c2, off);
    }
    if (lane == 0) {
        out[0] = c2;
    }
}

extern "C" void kernel_launch(void* const* d_in, const int* in_sizes, int n_in,
                              void* d_out, int out_size) {
    (void)in_sizes; (void)n_in; (void)out_size;
    const float* x = (const float*)d_in[0];
    const float* y = (const float*)d_in[1];
    // d_in[2] = params — unused: the shared circuit unitary cancels in the overlap.
    float* out = (float*)d_out;
    KernalAnsatz_65481071409588_kernel<<<1, 32>>>(x, y, out);
}